// round 14
// baseline (speedup 1.0000x reference)
#include <cuda_runtime.h>
#include <cfloat>
#include <math.h>
#include <stdint.h>

#define N_ROWS 65536
#define KDIM   512
#define NE     1024
#define NG     8          // column groups of 128 codes
#define TILES  1024       // row tiles of 64
#define SLOTS  16
#define MARGIN 4.0e-3f

#define SZF   15.875f                    // 127/8  (z scale)
#define SEF   130048.0f                  // 127*1024 (codebook scale)
#define INV2  (2.0f / (SZF * SEF))       // dequant factor for 2*dot

// ---------------- device scratch (no allocations allowed) ----------------
__device__ __align__(16) int g_zq[N_ROWS * (KDIM / 4)];   // packed int8x4
__device__ __align__(16) int g_eq[NE * (KDIM / 4)];
__device__ float g_bnorm[NE];
__device__ int   g_counts[NE];
__device__ int   g_tilecnt[TILES];
__device__ int   g_donecnt;
__device__ float g_partials[TILES];
__device__ float g_cmin[N_ROWS * NG];
__device__ int   g_ccnt[N_ROWS * NG];
__device__ float g_cd[(size_t)N_ROWS * NG * SLOTS];
__device__ int   g_cj[(size_t)N_ROWS * NG * SLOTS];

__device__ __forceinline__ int q8(float v, float s) {
    int q = __float2int_rn(v * s);
    return max(-127, min(127, q));
}
__device__ __forceinline__ int pack4(int a, int b, int c, int d) {
    return (a & 255) | ((b & 255) << 8) | ((c & 255) << 16) | ((d & 255) << 24);
}
__device__ __forceinline__ uint32_t smem_u32(const void* p) {
    uint32_t a;
    asm("{ .reg .u64 t; cvta.to.shared.u64 t, %1; cvt.u32.u64 %0, t; }" : "=r"(a) : "l"(p));
    return a;
}
__device__ __forceinline__ void cp_async4(uint32_t saddr, const void* gptr) {
    asm volatile("cp.async.ca.shared.global [%0], [%1], 4;"
                 :: "r"(saddr), "l"(__cvta_generic_to_global(gptr)) : "memory");
}

// ---------------- merged prep: quantize z + codebook, norms, zero scratch ----------------
__global__ void prep_kernel(const float* __restrict__ z, const float* __restrict__ cb) {
    const int bid = blockIdx.x;
    if (bid < 32768) {                               // z path: 4 floats/thread
        int t = bid * 256 + threadIdx.x;
        float4 v = ((const float4*)z)[t];
        g_zq[t] = pack4(q8(v.x, SZF), q8(v.y, SZF), q8(v.z, SZF), q8(v.w, SZF));
        return;
    }
    // codebook path: 2 rows per block (128 threads each)
    const int b = (bid - 32768) * 2 + (threadIdx.x >> 7);
    const int t = threadIdx.x & 127;
    const float4 v = *(const float4*)(cb + (size_t)b * KDIM + t * 4);
    g_eq[b * 128 + t] = pack4(q8(v.x, SEF), q8(v.y, SEF), q8(v.z, SEF), q8(v.w, SEF));
    float s = v.x * v.x + v.y * v.y + v.z * v.z + v.w * v.w;
#pragma unroll
    for (int o = 16; o; o >>= 1) s += __shfl_xor_sync(0xffffffffu, s, o);
    __shared__ float w[8];
    if ((threadIdx.x & 31) == 0) w[threadIdx.x >> 5] = s;
    __syncthreads();
    if (t == 0) {
        const int wb = (threadIdx.x >> 7) * 4;
        g_bnorm[b]  = (w[wb + 0] + w[wb + 1]) + (w[wb + 2] + w[wb + 3]);
        g_counts[b] = 0;
        if (b < TILES) g_tilecnt[b] = 0;
        if (b == 0) g_donecnt = 0;
    }
}

// ---------------- fused: dp4a GEMM (broadcast-B warp tiles) + candidates + tail ----------------
#define STRA 68                       // A smem stride (ints)
#define STRB 132                      // B smem stride (ints)
#define CHUNK 32                      // kp per chunk (int32 packs)
#define NCHUNK 4
#define ABUF (CHUNK * STRA)           // 2176 ints
#define BBUF (CHUNK * STRB)           // 4224 ints
#define STAGEI (ABUF + BBUF)          // 6400 ints per stage
#define GEMM_SMEM (2 * STAGEI * 4)    // 51200 B

extern __shared__ __align__(16) int smem_i[];

__global__ void __launch_bounds__(256, 4)
gemm_kernel(const float* __restrict__ z, const float* __restrict__ cb,
            float* __restrict__ out, int idx_base, int out_size) {
    const int tid = threadIdx.x;
    const int lane = tid & 31;        // row pair: rows 2*lane, 2*lane+1
    const int w    = tid >> 5;        // col group: cols w*16 .. w*16+15
    const int tile = blockIdx.x >> 3;
    const int row0 = tile * 64;
    const int cg   = blockIdx.x & 7;
    const uint32_t sb = smem_u32(smem_i);

    auto load_chunk = [&](int c) {
        const int st = c & 1;
        const uint32_t abase = sb + (uint32_t)(st * STAGEI) * 4;
        const uint32_t bbase = abase + (uint32_t)ABUF * 4;
        const int kp0 = c * CHUNK;
#pragma unroll
        for (int i = 0; i < 8; ++i) {            // A: 64 rows x 32 kp, smem [kp][row]
            int u = tid + i * 256;               // 0..2047
            int kp = u & 31, r = u >> 5;
            cp_async4(abase + (uint32_t)(kp * STRA + r) * 4,
                      g_zq + (size_t)(row0 + r) * 128 + kp0 + kp);
        }
#pragma unroll
        for (int i = 0; i < 16; ++i) {           // B: 128 cols x 32 kp, smem [kp][col]
            int u = tid + i * 256;               // 0..4095
            int kp = u & 31, r = u >> 5;
            cp_async4(bbase + (uint32_t)(kp * STRB + r) * 4,
                      g_eq + (size_t)(cg * 128 + r) * 128 + kp0 + kp);
        }
        asm volatile("cp.async.commit_group;" ::: "memory");
    };

    int acc[2][16];
#pragma unroll
    for (int i = 0; i < 2; ++i)
#pragma unroll
        for (int j = 0; j < 16; ++j) acc[i][j] = 0;

    load_chunk(0);

    for (int c = 0; c < NCHUNK; ++c) {
        if (c + 1 < NCHUNK) {
            load_chunk(c + 1);
            asm volatile("cp.async.wait_group 1;" ::: "memory");
        } else {
            asm volatile("cp.async.wait_group 0;" ::: "memory");
        }
        __syncthreads();

        const int st = c & 1;
        const int* ap = smem_i + st * STAGEI + 2 * lane;        // spread LDS.64 (conflict-free)
        const int* bp = smem_i + st * STAGEI + ABUF + w * 16;   // warp-uniform broadcast

#pragma unroll 4
        for (int kp = 0; kp < CHUNK; ++kp) {
            int a2[2], b16[16];
            *(int2*)(a2)       = *(const int2*)(ap + kp * STRA);
            *(int4*)(b16)      = *(const int4*)(bp + kp * STRB);
            *(int4*)(b16 + 4)  = *(const int4*)(bp + kp * STRB + 4);
            *(int4*)(b16 + 8)  = *(const int4*)(bp + kp * STRB + 8);
            *(int4*)(b16 + 12) = *(const int4*)(bp + kp * STRB + 12);
#pragma unroll
            for (int i = 0; i < 2; ++i)
#pragma unroll
                for (int j = 0; j < 16; ++j)
                    acc[i][j] = __dp4a(a2[i], b16[j], acc[i][j]);
        }
        __syncthreads();
    }

    // ---- epilogue: dequantized coarse distances -> smem ds[64][130] ----
    float* ds = (float*)smem_i;
    {
        float bn[16];
#pragma unroll
        for (int j = 0; j < 16; ++j) bn[j] = g_bnorm[cg * 128 + w * 16 + j];
#pragma unroll
        for (int i = 0; i < 2; ++i) {
            const int row = 2 * lane + i;
#pragma unroll
            for (int j = 0; j < 16; ++j)
                ds[row * 130 + w * 16 + j] = fmaf(-INV2, (float)acc[i][j], bn[j]);
        }
    }
    __syncthreads();

    // two-pass collection: true row min first, then collect within margin (col-ascending)
    if (tid < 64) {
        const int row = row0 + tid;
        float bmin = FLT_MAX;
#pragma unroll 8
        for (int c = 0; c < 128; ++c) bmin = fminf(bmin, ds[tid * 130 + c]);
        const float thr = bmin + MARGIN;
        int cnt = 0;
        const size_t base = ((size_t)row * NG + cg) * SLOTS;
        for (int c = 0; c < 128; ++c) {
            float d = ds[tid * 130 + c];
            if (d <= thr) {
                if (cnt < SLOTS) { g_cd[base + cnt] = d; g_cj[base + cnt] = cg * 128 + c; }
                cnt++;
            }
        }
        g_cmin[row * NG + cg] = bmin;
        g_ccnt[row * NG + cg] = cnt;
    }

    // publish, detect last CTA of this tile
    __threadfence();
    __syncthreads();
    __shared__ int s_last;
    if (tid == 0) s_last = (atomicAdd(&g_tilecnt[tile], 1) == NG - 1);
    __syncthreads();
    if (!s_last) return;
    __threadfence();

    // ---- tail: exact fp32 rescore + output for rows row0..row0+63 ----
    const int wid = tid >> 5, lid = tid & 31;
    float lsum = 0.f;

    for (int r = 0; r < 8; ++r) {
        const int row = row0 + wid * 8 + r;

        const float4* zr = (const float4*)(z + (size_t)row * KDIM) + lid;
        const float4 z0 = zr[0], z1 = zr[32], z2 = zr[64], z3 = zr[96];

        float s = 0.f;
        s = fmaf(z0.x, z0.x, s); s = fmaf(z0.y, z0.y, s); s = fmaf(z0.z, z0.z, s); s = fmaf(z0.w, z0.w, s);
        s = fmaf(z1.x, z1.x, s); s = fmaf(z1.y, z1.y, s); s = fmaf(z1.z, z1.z, s); s = fmaf(z1.w, z1.w, s);
        s = fmaf(z2.x, z2.x, s); s = fmaf(z2.y, z2.y, s); s = fmaf(z2.z, z2.z, s); s = fmaf(z2.w, z2.w, s);
        s = fmaf(z3.x, z3.x, s); s = fmaf(z3.y, z3.y, s); s = fmaf(z3.z, z3.z, s); s = fmaf(z3.w, z3.w, s);
#pragma unroll
        for (int o = 16; o; o >>= 1) s += __shfl_xor_sync(0xffffffffu, s, o);
        const float anorm = s;

        float gmin = FLT_MAX;
        float cmins[NG];
        int cnts[NG];
#pragma unroll
        for (int g = 0; g < NG; ++g) {
            cmins[g] = g_cmin[row * NG + g];
            cnts[g]  = g_ccnt[row * NG + g];
            if (cmins[g] < gmin) gmin = cmins[g];
        }
        const float thr = gmin + MARGIN;

        float bestd = FLT_MAX;
        int bestj = NE;
        auto eval = [&](int j) {
            const float4* cr = (const float4*)(cb + (size_t)j * KDIM) + lid;
            const float4 c0 = cr[0], c1 = cr[32], c2 = cr[64], c3 = cr[96];
            float t = 0.f;
            t = fmaf(z0.x, c0.x, t); t = fmaf(z0.y, c0.y, t); t = fmaf(z0.z, c0.z, t); t = fmaf(z0.w, c0.w, t);
            t = fmaf(z1.x, c1.x, t); t = fmaf(z1.y, c1.y, t); t = fmaf(z1.z, c1.z, t); t = fmaf(z1.w, c1.w, t);
            t = fmaf(z2.x, c2.x, t); t = fmaf(z2.y, c2.y, t); t = fmaf(z2.z, c2.z, t); t = fmaf(z2.w, c2.w, t);
            t = fmaf(z3.x, c3.x, t); t = fmaf(z3.y, c3.y, t); t = fmaf(z3.z, c3.z, t); t = fmaf(z3.w, c3.w, t);
#pragma unroll
            for (int o = 16; o; o >>= 1) t += __shfl_xor_sync(0xffffffffu, t, o);
            // d = fl(fl(a + b) - 2c), exactly mirroring the reference
            float d = __fadd_rn(__fadd_rn(anorm, g_bnorm[j]), -2.0f * t);
            if (d < bestd || (d == bestd && j < bestj)) { bestd = d; bestj = j; }
        };

        for (int g = 0; g < NG; ++g) {
            if (cmins[g] > thr) continue;
            if (cnts[g] <= SLOTS) {
                const size_t base = ((size_t)row * NG + g) * SLOTS;
                for (int sI = 0; sI < cnts[g]; ++sI)
                    if (g_cd[base + sI] <= thr) eval(g_cj[base + sI]);
            } else {
                for (int c = 0; c < 128; ++c) eval(g * 128 + c);   // rare overflow
            }
        }

        // output: z_q_st (scalar stores; out+1 is float4-misaligned), loss partial
        const float4* cr = (const float4*)(cb + (size_t)bestj * KDIM) + lid;
        const float4 c0 = cr[0], c1 = cr[32], c2 = cr[64], c3 = cr[96];
        float* dst = out + 1 + (size_t)row * KDIM;
        {
            float t0 = __fsub_rn(c0.x, z0.x), t1 = __fsub_rn(c0.y, z0.y);
            float t2 = __fsub_rn(c0.z, z0.z), t3 = __fsub_rn(c0.w, z0.w);
            dst[4*lid+0] = __fadd_rn(z0.x, t0); dst[4*lid+1] = __fadd_rn(z0.y, t1);
            dst[4*lid+2] = __fadd_rn(z0.z, t2); dst[4*lid+3] = __fadd_rn(z0.w, t3);
            lsum += t0*t0 + t1*t1 + t2*t2 + t3*t3;
        }
        {
            float t0 = __fsub_rn(c1.x, z1.x), t1 = __fsub_rn(c1.y, z1.y);
            float t2 = __fsub_rn(c1.z, z1.z), t3 = __fsub_rn(c1.w, z1.w);
            dst[128+4*lid+0] = __fadd_rn(z1.x, t0); dst[128+4*lid+1] = __fadd_rn(z1.y, t1);
            dst[128+4*lid+2] = __fadd_rn(z1.z, t2); dst[128+4*lid+3] = __fadd_rn(z1.w, t3);
            lsum += t0*t0 + t1*t1 + t2*t2 + t3*t3;
        }
        {
            float t0 = __fsub_rn(c2.x, z2.x), t1 = __fsub_rn(c2.y, z2.y);
            float t2 = __fsub_rn(c2.z, z2.z), t3 = __fsub_rn(c2.w, z2.w);
            dst[256+4*lid+0] = __fadd_rn(z2.x, t0); dst[256+4*lid+1] = __fadd_rn(z2.y, t1);
            dst[256+4*lid+2] = __fadd_rn(z2.z, t2); dst[256+4*lid+3] = __fadd_rn(z2.w, t3);
            lsum += t0*t0 + t1*t1 + t2*t2 + t3*t3;
        }
        {
            float t0 = __fsub_rn(c3.x, z3.x), t1 = __fsub_rn(c3.y, z3.y);
            float t2 = __fsub_rn(c3.z, z3.z), t3 = __fsub_rn(c3.w, z3.w);
            dst[384+4*lid+0] = __fadd_rn(z3.x, t0); dst[384+4*lid+1] = __fadd_rn(z3.y, t1);
            dst[384+4*lid+2] = __fadd_rn(z3.z, t2); dst[384+4*lid+3] = __fadd_rn(z3.w, t3);
            lsum += t0*t0 + t1*t1 + t2*t2 + t3*t3;
        }

        if (lid == 0) {
            out[idx_base + row] = (float)bestj;
            atomicAdd(&g_counts[bestj], 1);
        }
    }

    // deterministic tile loss partial: lane-sum -> warp shfl -> fixed-order 8-warp sum
#pragma unroll
    for (int o = 16; o; o >>= 1) lsum += __shfl_xor_sync(0xffffffffu, lsum, o);
    __shared__ float red[8];
    if (lid == 0) red[wid] = lsum;
    __syncthreads();
    if (tid == 0) {
        float t = 0.f;
#pragma unroll
        for (int ww = 0; ww < 8; ++ww) t += red[ww];
        g_partials[tile] = t;
    }

    // ---- finalize (the CTA completing the last tile): loss + perplexity ----
    __threadfence();
    __syncthreads();
    __shared__ int s_fin;
    if (tid == 0) s_fin = (atomicAdd(&g_donecnt, 1) == TILES - 1);
    __syncthreads();
    if (!s_fin) return;
    __threadfence();

    __shared__ float red2[256];
    {
        float p = ((g_partials[tid] + g_partials[tid + 256])
                 + (g_partials[tid + 512] + g_partials[tid + 768]));
        red2[tid] = p;
        __syncthreads();
#pragma unroll
        for (int o = 128; o; o >>= 1) {
            if (tid < o) red2[tid] += red2[tid + o];
            __syncthreads();
        }
    }
    const float total = red2[0];
    __syncthreads();
    {
        float ent = 0.f;
#pragma unroll
        for (int q = 0; q < 4; ++q) {
            float e = (float)g_counts[tid + q * 256] * (1.0f / 65536.0f);
            ent += e * logf(e + 1e-10f);
        }
        red2[tid] = ent;
        __syncthreads();
#pragma unroll
        for (int o = 128; o; o >>= 1) {
            if (tid < o) red2[tid] += red2[tid + o];
            __syncthreads();
        }
    }
    if (tid == 0) {
        float m = total / 33554432.0f;
        out[0] = __fadd_rn(m, __fmul_rn(0.25f, m));
        out[out_size - 1] = expf(-red2[0]);
    }
}

// ---------------- launch ----------------
extern "C" void kernel_launch(void* const* d_in, const int* in_sizes, int n_in,
                              void* d_out, int out_size) {
    const float* z  = (const float*)d_in[0];
    const float* cb = (const float*)d_in[1];
    float* out = (float*)d_out;
    const int idx_base = out_size - 1 - N_ROWS;

    cudaFuncSetAttribute(gemm_kernel, cudaFuncAttributeMaxDynamicSharedMemorySize, GEMM_SMEM);

    prep_kernel<<<33280, 256>>>(z, cb);                                      // 0
    gemm_kernel<<<8192, 256, GEMM_SMEM>>>(z, cb, out, idx_base, out_size);   // 1
}

// round 15
// speedup vs baseline: 1.0085x; 1.0085x over previous
#include <cuda_runtime.h>
#include <cfloat>
#include <math.h>
#include <stdint.h>

#define N_ROWS 65536
#define KDIM   512
#define NE     1024
#define NG     8          // column groups of 128 codes
#define TILES  1024       // row tiles of 64
#define SLOTS  16
#define MARGIN 4.0e-3f

#define SZF   15.875f                    // 127/8  (z scale)
#define SEF   130048.0f                  // 127*1024 (codebook scale)
#define INV2  (2.0f / (SZF * SEF))       // dequant factor for 2*dot

// ---------------- device scratch (no allocations allowed) ----------------
__device__ __align__(16) int g_zq[N_ROWS * (KDIM / 4)];   // packed int8x4
__device__ __align__(16) int g_eq[NE * (KDIM / 4)];
__device__ float g_bnorm[NE];
__device__ int   g_counts[NE];
__device__ int   g_tilecnt[TILES];
__device__ int   g_donecnt;
__device__ float g_partials[TILES];
__device__ float g_cmin[N_ROWS * NG];
__device__ int   g_ccnt[N_ROWS * NG];
__device__ float g_cd[(size_t)N_ROWS * NG * SLOTS];
__device__ int   g_cj[(size_t)N_ROWS * NG * SLOTS];

__device__ __forceinline__ int q8(float v, float s) {
    int q = __float2int_rn(v * s);
    return max(-127, min(127, q));
}
__device__ __forceinline__ int pack4(int a, int b, int c, int d) {
    return (a & 255) | ((b & 255) << 8) | ((c & 255) << 16) | ((d & 255) << 24);
}
__device__ __forceinline__ uint32_t smem_u32(const void* p) {
    uint32_t a;
    asm("{ .reg .u64 t; cvta.to.shared.u64 t, %1; cvt.u32.u64 %0, t; }" : "=r"(a) : "l"(p));
    return a;
}
__device__ __forceinline__ void cp_async4(uint32_t saddr, const void* gptr) {
    asm volatile("cp.async.ca.shared.global [%0], [%1], 4;"
                 :: "r"(saddr), "l"(__cvta_generic_to_global(gptr)) : "memory");
}

// ---------------- merged prep: quantize z (2x float4/thread) + codebook ----------------
__global__ void prep_kernel(const float* __restrict__ z, const float* __restrict__ cb) {
    const int bid = blockIdx.x;
    if (bid < 16384) {                               // z path: 8 floats/thread (2 x float4)
        int t = bid * 512 + threadIdx.x * 2;
        const float4* zp = (const float4*)z;
        float4 v0 = zp[t];
        float4 v1 = zp[t + 1];
        g_zq[t]     = pack4(q8(v0.x, SZF), q8(v0.y, SZF), q8(v0.z, SZF), q8(v0.w, SZF));
        g_zq[t + 1] = pack4(q8(v1.x, SZF), q8(v1.y, SZF), q8(v1.z, SZF), q8(v1.w, SZF));
        return;
    }
    // codebook path: 2 rows per block (128 threads each)
    const int b = (bid - 16384) * 2 + (threadIdx.x >> 7);
    const int t = threadIdx.x & 127;
    const float4 v = *(const float4*)(cb + (size_t)b * KDIM + t * 4);
    g_eq[b * 128 + t] = pack4(q8(v.x, SEF), q8(v.y, SEF), q8(v.z, SEF), q8(v.w, SEF));
    float s = v.x * v.x + v.y * v.y + v.z * v.z + v.w * v.w;
#pragma unroll
    for (int o = 16; o; o >>= 1) s += __shfl_xor_sync(0xffffffffu, s, o);
    __shared__ float w[8];
    if ((threadIdx.x & 31) == 0) w[threadIdx.x >> 5] = s;
    __syncthreads();
    if (t == 0) {
        const int wb = (threadIdx.x >> 7) * 4;
        g_bnorm[b]  = (w[wb + 0] + w[wb + 1]) + (w[wb + 2] + w[wb + 3]);
        g_counts[b] = 0;
        if (b < TILES) g_tilecnt[b] = 0;
        if (b == 0) g_donecnt = 0;
    }
}

// ---------------- fused: dp4a GEMM + candidates + last-CTA tail + last-tile finalize ----------------
#define STRA 68                       // A smem stride (ints), 16B-aligned rows
#define STRB 132                      // B smem stride (ints)
#define CHUNK 32                      // kp per chunk (int32 packs)
#define NCHUNK 4
#define ABUF (CHUNK * STRA)           // 2176 ints
#define BBUF (CHUNK * STRB)           // 4224 ints
#define STAGEI (ABUF + BBUF)          // 6400 ints per stage
#define GEMM_SMEM (2 * STAGEI * 4)    // 51200 B

extern __shared__ __align__(16) int smem_i[];

__global__ void __launch_bounds__(256, 4)
gemm_kernel(const float* __restrict__ z, const float* __restrict__ cb,
            float* __restrict__ out, int idx_base, int out_size) {
    const int tid = threadIdx.x;
    const int tx = tid & 31;          // 32 col groups x 4 cols
    const int ty = tid >> 5;          // 8 row groups x 8 rows (== warp id)
    const int tile = blockIdx.x >> 3;
    const int row0 = tile * 64;
    const int cg   = blockIdx.x & 7;
    const uint32_t sb = smem_u32(smem_i);

    auto load_chunk = [&](int c) {
        const int st = c & 1;
        const uint32_t abase = sb + (uint32_t)(st * STAGEI) * 4;
        const uint32_t bbase = abase + (uint32_t)ABUF * 4;
        const int kp0 = c * CHUNK;
#pragma unroll
        for (int i = 0; i < 8; ++i) {            // A: 64 rows x 32 kp
            int u = tid + i * 256;               // 0..2047
            int kp = u & 31, r = u >> 5;
            cp_async4(abase + (uint32_t)(kp * STRA + r) * 4,
                      g_zq + (size_t)(row0 + r) * 128 + kp0 + kp);
        }
#pragma unroll
        for (int i = 0; i < 16; ++i) {           // B: 128 cols x 32 kp
            int u = tid + i * 256;               // 0..4095
            int kp = u & 31, r = u >> 5;
            cp_async4(bbase + (uint32_t)(kp * STRB + r) * 4,
                      g_eq + (size_t)(cg * 128 + r) * 128 + kp0 + kp);
        }
        asm volatile("cp.async.commit_group;" ::: "memory");
    };

    int acc[8][4];
#pragma unroll
    for (int i = 0; i < 8; ++i)
#pragma unroll
        for (int j = 0; j < 4; ++j) acc[i][j] = 0;

    load_chunk(0);

    for (int c = 0; c < NCHUNK; ++c) {
        if (c + 1 < NCHUNK) {
            load_chunk(c + 1);
            asm volatile("cp.async.wait_group 1;" ::: "memory");
        } else {
            asm volatile("cp.async.wait_group 0;" ::: "memory");
        }
        __syncthreads();

        const int st = c & 1;
        const int* ap = smem_i + st * STAGEI + ty * 8;          // broadcast loads (warp-uniform)
        const int* bp = smem_i + st * STAGEI + ABUF + tx * 4;

#pragma unroll 4
        for (int kp = 0; kp < CHUNK; ++kp) {
            int a[8], b[4];
            *(int4*)(a)     = *(const int4*)(ap + kp * STRA);
            *(int4*)(a + 4) = *(const int4*)(ap + kp * STRA + 4);
            *(int4*)(b)     = *(const int4*)(bp + kp * STRB);
#pragma unroll
            for (int i = 0; i < 8; ++i)
#pragma unroll
                for (int j = 0; j < 4; ++j)
                    acc[i][j] = __dp4a(a[i], b[j], acc[i][j]);
        }
        __syncthreads();
    }

    // ---- register epilogue: one warp owns 8 rows; full-warp min + ballot collection ----
    {
        float bn[4];
#pragma unroll
        for (int j = 0; j < 4; ++j) bn[j] = g_bnorm[cg * 128 + tx * 4 + j];
        const unsigned below = (1u << tx) - 1u;

#pragma unroll
        for (int i = 0; i < 8; ++i) {
            const int row = row0 + ty * 8 + i;
            float d[4];
            float m = FLT_MAX;
#pragma unroll
            for (int j = 0; j < 4; ++j) {
                d[j] = fmaf(-INV2, (float)acc[i][j], bn[j]);
                m = fminf(m, d[j]);
            }
#pragma unroll
            for (int off = 1; off < 32; off <<= 1)
                m = fminf(m, __shfl_xor_sync(0xffffffffu, m, off));
            const float thr = m + MARGIN;
            int cnt = 0;
            const size_t base = ((size_t)row * NG + cg) * SLOTS;
#pragma unroll
            for (int j = 0; j < 4; ++j) {
                bool p = d[j] <= thr;
                unsigned bal = __ballot_sync(0xffffffffu, p);
                if (p) {
                    int slot = cnt + __popc(bal & below);
                    if (slot < SLOTS) {
                        g_cd[base + slot] = d[j];
                        g_cj[base + slot] = cg * 128 + tx * 4 + j;
                    }
                }
                cnt += __popc(bal);
            }
            if (tx == 0) {
                g_cmin[row * NG + cg] = m;
                g_ccnt[row * NG + cg] = cnt;
            }
        }
    }

    // publish, detect last CTA of this tile
    __threadfence();
    __syncthreads();
    __shared__ int s_last;
    if (tid == 0) s_last = (atomicAdd(&g_tilecnt[tile], 1) == NG - 1);
    __syncthreads();
    if (!s_last) return;
    __threadfence();

    // ---- tail: exact fp32 rescore + output for rows row0..row0+63 ----
    const int wid = tid >> 5, lid = tid & 31;
    float lsum = 0.f;

    for (int r = 0; r < 8; ++r) {
        const int row = row0 + wid * 8 + r;

        const float4* zr = (const float4*)(z + (size_t)row * KDIM) + lid;
        const float4 z0 = zr[0], z1 = zr[32], z2 = zr[64], z3 = zr[96];

        float s = 0.f;
        s = fmaf(z0.x, z0.x, s); s = fmaf(z0.y, z0.y, s); s = fmaf(z0.z, z0.z, s); s = fmaf(z0.w, z0.w, s);
        s = fmaf(z1.x, z1.x, s); s = fmaf(z1.y, z1.y, s); s = fmaf(z1.z, z1.z, s); s = fmaf(z1.w, z1.w, s);
        s = fmaf(z2.x, z2.x, s); s = fmaf(z2.y, z2.y, s); s = fmaf(z2.z, z2.z, s); s = fmaf(z2.w, z2.w, s);
        s = fmaf(z3.x, z3.x, s); s = fmaf(z3.y, z3.y, s); s = fmaf(z3.z, z3.z, s); s = fmaf(z3.w, z3.w, s);
#pragma unroll
        for (int o = 16; o; o >>= 1) s += __shfl_xor_sync(0xffffffffu, s, o);
        const float anorm = s;

        float gmin = FLT_MAX;
        float cmins[NG];
        int cnts[NG];
#pragma unroll
        for (int g = 0; g < NG; ++g) {
            cmins[g] = g_cmin[row * NG + g];
            cnts[g]  = g_ccnt[row * NG + g];
            if (cmins[g] < gmin) gmin = cmins[g];
        }
        const float thr = gmin + MARGIN;

        float bestd = FLT_MAX;
        int bestj = NE;
        auto eval = [&](int j) {
            const float4* cr = (const float4*)(cb + (size_t)j * KDIM) + lid;
            const float4 c0 = cr[0], c1 = cr[32], c2 = cr[64], c3 = cr[96];
            float t = 0.f;
            t = fmaf(z0.x, c0.x, t); t = fmaf(z0.y, c0.y, t); t = fmaf(z0.z, c0.z, t); t = fmaf(z0.w, c0.w, t);
            t = fmaf(z1.x, c1.x, t); t = fmaf(z1.y, c1.y, t); t = fmaf(z1.z, c1.z, t); t = fmaf(z1.w, c1.w, t);
            t = fmaf(z2.x, c2.x, t); t = fmaf(z2.y, c2.y, t); t = fmaf(z2.z, c2.z, t); t = fmaf(z2.w, c2.w, t);
            t = fmaf(z3.x, c3.x, t); t = fmaf(z3.y, c3.y, t); t = fmaf(z3.z, c3.z, t); t = fmaf(z3.w, c3.w, t);
#pragma unroll
            for (int o = 16; o; o >>= 1) t += __shfl_xor_sync(0xffffffffu, t, o);
            // d = fl(fl(a + b) - 2c), exactly mirroring the reference
            float d = __fadd_rn(__fadd_rn(anorm, g_bnorm[j]), -2.0f * t);
            if (d < bestd || (d == bestd && j < bestj)) { bestd = d; bestj = j; }
        };

        for (int g = 0; g < NG; ++g) {
            if (cmins[g] > thr) continue;
            if (cnts[g] <= SLOTS) {
                const size_t base = ((size_t)row * NG + g) * SLOTS;
                for (int sI = 0; sI < cnts[g]; ++sI)
                    if (g_cd[base + sI] <= thr) eval(g_cj[base + sI]);
            } else {
                for (int c = 0; c < 128; ++c) eval(g * 128 + c);   // rare overflow
            }
        }

        // output: z_q_st (scalar stores; out+1 is float4-misaligned), loss partial
        const float4* cr = (const float4*)(cb + (size_t)bestj * KDIM) + lid;
        const float4 c0 = cr[0], c1 = cr[32], c2 = cr[64], c3 = cr[96];
        float* dst = out + 1 + (size_t)row * KDIM;
        {
            float t0 = __fsub_rn(c0.x, z0.x), t1 = __fsub_rn(c0.y, z0.y);
            float t2 = __fsub_rn(c0.z, z0.z), t3 = __fsub_rn(c0.w, z0.w);
            dst[4*lid+0] = __fadd_rn(z0.x, t0); dst[4*lid+1] = __fadd_rn(z0.y, t1);
            dst[4*lid+2] = __fadd_rn(z0.z, t2); dst[4*lid+3] = __fadd_rn(z0.w, t3);
            lsum += t0*t0 + t1*t1 + t2*t2 + t3*t3;
        }
        {
            float t0 = __fsub_rn(c1.x, z1.x), t1 = __fsub_rn(c1.y, z1.y);
            float t2 = __fsub_rn(c1.z, z1.z), t3 = __fsub_rn(c1.w, z1.w);
            dst[128+4*lid+0] = __fadd_rn(z1.x, t0); dst[128+4*lid+1] = __fadd_rn(z1.y, t1);
            dst[128+4*lid+2] = __fadd_rn(z1.z, t2); dst[128+4*lid+3] = __fadd_rn(z1.w, t3);
            lsum += t0*t0 + t1*t1 + t2*t2 + t3*t3;
        }
        {
            float t0 = __fsub_rn(c2.x, z2.x), t1 = __fsub_rn(c2.y, z2.y);
            float t2 = __fsub_rn(c2.z, z2.z), t3 = __fsub_rn(c2.w, z2.w);
            dst[256+4*lid+0] = __fadd_rn(z2.x, t0); dst[256+4*lid+1] = __fadd_rn(z2.y, t1);
            dst[256+4*lid+2] = __fadd_rn(z2.z, t2); dst[256+4*lid+3] = __fadd_rn(z2.w, t3);
            lsum += t0*t0 + t1*t1 + t2*t2 + t3*t3;
        }
        {
            float t0 = __fsub_rn(c3.x, z3.x), t1 = __fsub_rn(c3.y, z3.y);
            float t2 = __fsub_rn(c3.z, z3.z), t3 = __fsub_rn(c3.w, z3.w);
            dst[384+4*lid+0] = __fadd_rn(z3.x, t0); dst[384+4*lid+1] = __fadd_rn(z3.y, t1);
            dst[384+4*lid+2] = __fadd_rn(z3.z, t2); dst[384+4*lid+3] = __fadd_rn(z3.w, t3);
            lsum += t0*t0 + t1*t1 + t2*t2 + t3*t3;
        }

        if (lid == 0) {
            out[idx_base + row] = (float)bestj;
            atomicAdd(&g_counts[bestj], 1);
        }
    }

    // deterministic tile loss partial: lane-sum -> warp shfl -> fixed-order 8-warp sum
#pragma unroll
    for (int o = 16; o; o >>= 1) lsum += __shfl_xor_sync(0xffffffffu, lsum, o);
    __shared__ float red[8];
    if (lid == 0) red[wid] = lsum;
    __syncthreads();
    if (tid == 0) {
        float t = 0.f;
#pragma unroll
        for (int w = 0; w < 8; ++w) t += red[w];
        g_partials[tile] = t;
    }

    // ---- finalize (the CTA completing the last tile): loss + perplexity ----
    __threadfence();
    __syncthreads();
    __shared__ int s_fin;
    if (tid == 0) s_fin = (atomicAdd(&g_donecnt, 1) == TILES - 1);
    __syncthreads();
    if (!s_fin) return;
    __threadfence();

    __shared__ float red2[256];
    {
        float p = ((g_partials[tid] + g_partials[tid + 256])
                 + (g_partials[tid + 512] + g_partials[tid + 768]));
        red2[tid] = p;
        __syncthreads();
#pragma unroll
        for (int o = 128; o; o >>= 1) {
            if (tid < o) red2[tid] += red2[tid + o];
            __syncthreads();
        }
    }
    const float total = red2[0];
    __syncthreads();
    {
        float ent = 0.f;
#pragma unroll
        for (int q = 0; q < 4; ++q) {
            float e = (float)g_counts[tid + q * 256] * (1.0f / 65536.0f);
            ent += e * logf(e + 1e-10f);
        }
        red2[tid] = ent;
        __syncthreads();
#pragma unroll
        for (int o = 128; o; o >>= 1) {
            if (tid < o) red2[tid] += red2[tid + o];
            __syncthreads();
        }
    }
    if (tid == 0) {
        float m = total / 33554432.0f;
        out[0] = __fadd_rn(m, __fmul_rn(0.25f, m));
        out[out_size - 1] = expf(-red2[0]);
    }
}

// ---------------- launch ----------------
extern "C" void kernel_launch(void* const* d_in, const int* in_sizes, int n_in,
                              void* d_out, int out_size) {
    const float* z  = (const float*)d_in[0];
    const float* cb = (const float*)d_in[1];
    float* out = (float*)d_out;
    const int idx_base = out_size - 1 - N_ROWS;

    cudaFuncSetAttribute(gemm_kernel, cudaFuncAttributeMaxDynamicSharedMemorySize, GEMM_SMEM);

    prep_kernel<<<16896, 256>>>(z, cb);                                      // 0
    gemm_kernel<<<8192, 256, GEMM_SMEM>>>(z, cb, out, idx_base, out_size);   // 1
}

// round 16
// speedup vs baseline: 1.0454x; 1.0367x over previous
#include <cuda_runtime.h>
#include <cfloat>
#include <math.h>
#include <stdint.h>

#define N_ROWS 65536
#define KDIM   512
#define NE     1024
#define NG     8          // column groups of 128 codes
#define TILES  1024       // row tiles of 64
#define SLOTS  16
#define MARGIN 4.0e-3f

#define SZF   15.875f                    // 127/8  (z scale)
#define SEF   130048.0f                  // 127*1024 (codebook scale)
#define INV2  (2.0f / (SZF * SEF))       // dequant factor for 2*dot

// ---------------- device scratch (no allocations allowed) ----------------
__device__ __align__(16) int g_zq[N_ROWS * (KDIM / 4)];   // packed int8x4
__device__ __align__(16) int g_eq[NE * (KDIM / 4)];
__device__ float g_bnorm[NE];
__device__ int   g_counts[NE];
__device__ int   g_tilecnt[TILES];
__device__ int   g_donecnt;
__device__ float g_partials[TILES];
__device__ float g_cmin[N_ROWS * NG];
__device__ int   g_ccnt[N_ROWS * NG];
__device__ float g_cd[(size_t)N_ROWS * NG * SLOTS];
__device__ int   g_cj[(size_t)N_ROWS * NG * SLOTS];

__device__ __forceinline__ int q8(float v, float s) {
    int q = __float2int_rn(v * s);
    return max(-127, min(127, q));
}
__device__ __forceinline__ int pack4(int a, int b, int c, int d) {
    return (a & 255) | ((b & 255) << 8) | ((c & 255) << 16) | ((d & 255) << 24);
}
__device__ __forceinline__ uint32_t smem_u32(const void* p) {
    uint32_t a;
    asm("{ .reg .u64 t; cvta.to.shared.u64 t, %1; cvt.u32.u64 %0, t; }" : "=r"(a) : "l"(p));
    return a;
}
__device__ __forceinline__ void cp_async4(uint32_t saddr, const void* gptr) {
    asm volatile("cp.async.ca.shared.global [%0], [%1], 4;"
                 :: "r"(saddr), "l"(__cvta_generic_to_global(gptr)) : "memory");
}

// ---------------- merged prep: quantize z (4x float4/thread, interleaved) + codebook ----------------
__global__ void prep_kernel(const float* __restrict__ z, const float* __restrict__ cb) {
    const int bid = blockIdx.x;
    if (bid < 8192) {                                // z path: 16 floats/thread, MLP=4
        const int base = bid * 1024 + threadIdx.x;   // float4 indices base+0,256,512,768
        const float4* zp = (const float4*)z;
        float4 v0 = zp[base];
        float4 v1 = zp[base + 256];
        float4 v2 = zp[base + 512];
        float4 v3 = zp[base + 768];
        g_zq[base]       = pack4(q8(v0.x, SZF), q8(v0.y, SZF), q8(v0.z, SZF), q8(v0.w, SZF));
        g_zq[base + 256] = pack4(q8(v1.x, SZF), q8(v1.y, SZF), q8(v1.z, SZF), q8(v1.w, SZF));
        g_zq[base + 512] = pack4(q8(v2.x, SZF), q8(v2.y, SZF), q8(v2.z, SZF), q8(v2.w, SZF));
        g_zq[base + 768] = pack4(q8(v3.x, SZF), q8(v3.y, SZF), q8(v3.z, SZF), q8(v3.w, SZF));
        return;
    }
    // codebook path: 2 rows per block (128 threads each)
    const int b = (bid - 8192) * 2 + (threadIdx.x >> 7);
    const int t = threadIdx.x & 127;
    const float4 v = *(const float4*)(cb + (size_t)b * KDIM + t * 4);
    g_eq[b * 128 + t] = pack4(q8(v.x, SEF), q8(v.y, SEF), q8(v.z, SEF), q8(v.w, SEF));
    float s = v.x * v.x + v.y * v.y + v.z * v.z + v.w * v.w;
#pragma unroll
    for (int o = 16; o; o >>= 1) s += __shfl_xor_sync(0xffffffffu, s, o);
    __shared__ float w[8];
    if ((threadIdx.x & 31) == 0) w[threadIdx.x >> 5] = s;
    __syncthreads();
    if (t == 0) {
        const int wb = (threadIdx.x >> 7) * 4;
        g_bnorm[b]  = (w[wb + 0] + w[wb + 1]) + (w[wb + 2] + w[wb + 3]);
        g_counts[b] = 0;
        if (b < TILES) g_tilecnt[b] = 0;
        if (b == 0) g_donecnt = 0;
    }
}

// ---------------- fused: dp4a GEMM + candidates + last-CTA tail + last-tile finalize ----------------
#define STRA 68                       // A smem stride (ints), 16B-aligned rows
#define STRB 132                      // B smem stride (ints)
#define CHUNK 32                      // kp per chunk (int32 packs)
#define NCHUNK 4
#define ABUF (CHUNK * STRA)           // 2176 ints
#define BBUF (CHUNK * STRB)           // 4224 ints
#define STAGEI (ABUF + BBUF)          // 6400 ints per stage
#define GEMM_SMEM (2 * STAGEI * 4)    // 51200 B

extern __shared__ __align__(16) int smem_i[];

__global__ void __launch_bounds__(256, 4)
gemm_kernel(const float* __restrict__ z, const float* __restrict__ cb,
            float* __restrict__ out, int idx_base, int out_size) {
    const int tid = threadIdx.x;
    const int tx = tid & 31;          // 32 col groups x 4 cols
    const int ty = tid >> 5;          // 8 row groups x 8 rows (== warp id)
    const int tile = blockIdx.x >> 3;
    const int row0 = tile * 64;
    const int cg   = blockIdx.x & 7;
    const uint32_t sb = smem_u32(smem_i);

    auto load_chunk = [&](int c) {
        const int st = c & 1;
        const uint32_t abase = sb + (uint32_t)(st * STAGEI) * 4;
        const uint32_t bbase = abase + (uint32_t)ABUF * 4;
        const int kp0 = c * CHUNK;
#pragma unroll
        for (int i = 0; i < 8; ++i) {            // A: 64 rows x 32 kp
            int u = tid + i * 256;               // 0..2047
            int kp = u & 31, r = u >> 5;
            cp_async4(abase + (uint32_t)(kp * STRA + r) * 4,
                      g_zq + (size_t)(row0 + r) * 128 + kp0 + kp);
        }
#pragma unroll
        for (int i = 0; i < 16; ++i) {           // B: 128 cols x 32 kp
            int u = tid + i * 256;               // 0..4095
            int kp = u & 31, r = u >> 5;
            cp_async4(bbase + (uint32_t)(kp * STRB + r) * 4,
                      g_eq + (size_t)(cg * 128 + r) * 128 + kp0 + kp);
        }
        asm volatile("cp.async.commit_group;" ::: "memory");
    };

    int acc[8][4];
#pragma unroll
    for (int i = 0; i < 8; ++i)
#pragma unroll
        for (int j = 0; j < 4; ++j) acc[i][j] = 0;

    load_chunk(0);

#pragma unroll
    for (int c = 0; c < NCHUNK; ++c) {
        if (c + 1 < NCHUNK) {
            load_chunk(c + 1);
            asm volatile("cp.async.wait_group 1;" ::: "memory");
        } else {
            asm volatile("cp.async.wait_group 0;" ::: "memory");
        }
        __syncthreads();

        const int st = c & 1;
        const int* ap = smem_i + st * STAGEI + ty * 8;          // broadcast loads (warp-uniform)
        const int* bp = smem_i + st * STAGEI + ABUF + tx * 4;

#pragma unroll 4
        for (int kp = 0; kp < CHUNK; ++kp) {
            int a[8], b[4];
            *(int4*)(a)     = *(const int4*)(ap + kp * STRA);
            *(int4*)(a + 4) = *(const int4*)(ap + kp * STRA + 4);
            *(int4*)(b)     = *(const int4*)(bp + kp * STRB);
#pragma unroll
            for (int i = 0; i < 8; ++i)
#pragma unroll
                for (int j = 0; j < 4; ++j)
                    acc[i][j] = __dp4a(a[i], b[j], acc[i][j]);
        }
        if (c + 1 < NCHUNK) __syncthreads();     // last chunk: no buffer reuse follows
    }

    // ---- register epilogue: one warp owns 8 rows; full-warp min + ballot collection ----
    {
        float bn[4];
#pragma unroll
        for (int j = 0; j < 4; ++j) bn[j] = g_bnorm[cg * 128 + tx * 4 + j];
        const unsigned below = (1u << tx) - 1u;

#pragma unroll
        for (int i = 0; i < 8; ++i) {
            const int row = row0 + ty * 8 + i;
            float d[4];
            float m = FLT_MAX;
#pragma unroll
            for (int j = 0; j < 4; ++j) {
                d[j] = fmaf(-INV2, (float)acc[i][j], bn[j]);
                m = fminf(m, d[j]);
            }
#pragma unroll
            for (int off = 1; off < 32; off <<= 1)
                m = fminf(m, __shfl_xor_sync(0xffffffffu, m, off));
            const float thr = m + MARGIN;
            int cnt = 0;
            const size_t base = ((size_t)row * NG + cg) * SLOTS;
#pragma unroll
            for (int j = 0; j < 4; ++j) {
                bool p = d[j] <= thr;
                unsigned bal = __ballot_sync(0xffffffffu, p);
                if (p) {
                    int slot = cnt + __popc(bal & below);
                    if (slot < SLOTS) {
                        g_cd[base + slot] = d[j];
                        g_cj[base + slot] = cg * 128 + tx * 4 + j;
                    }
                }
                cnt += __popc(bal);
            }
            if (tx == 0) {
                g_cmin[row * NG + cg] = m;
                g_ccnt[row * NG + cg] = cnt;
            }
        }
    }

    // publish, detect last CTA of this tile
    __threadfence();
    __syncthreads();
    __shared__ int s_last;
    if (tid == 0) s_last = (atomicAdd(&g_tilecnt[tile], 1) == NG - 1);
    __syncthreads();
    if (!s_last) return;
    __threadfence();

    // ---- tail: exact fp32 rescore + output for rows row0..row0+63 ----
    const int wid = tid >> 5, lid = tid & 31;
    float lsum = 0.f;

    for (int r = 0; r < 8; ++r) {
        const int row = row0 + wid * 8 + r;

        const float4* zr = (const float4*)(z + (size_t)row * KDIM) + lid;
        const float4 z0 = zr[0], z1 = zr[32], z2 = zr[64], z3 = zr[96];

        float s = 0.f;
        s = fmaf(z0.x, z0.x, s); s = fmaf(z0.y, z0.y, s); s = fmaf(z0.z, z0.z, s); s = fmaf(z0.w, z0.w, s);
        s = fmaf(z1.x, z1.x, s); s = fmaf(z1.y, z1.y, s); s = fmaf(z1.z, z1.z, s); s = fmaf(z1.w, z1.w, s);
        s = fmaf(z2.x, z2.x, s); s = fmaf(z2.y, z2.y, s); s = fmaf(z2.z, z2.z, s); s = fmaf(z2.w, z2.w, s);
        s = fmaf(z3.x, z3.x, s); s = fmaf(z3.y, z3.y, s); s = fmaf(z3.z, z3.z, s); s = fmaf(z3.w, z3.w, s);
#pragma unroll
        for (int o = 16; o; o >>= 1) s += __shfl_xor_sync(0xffffffffu, s, o);
        const float anorm = s;

        float gmin = FLT_MAX;
        float cmins[NG];
        int cnts[NG];
#pragma unroll
        for (int g = 0; g < NG; ++g) {
            cmins[g] = g_cmin[row * NG + g];
            cnts[g]  = g_ccnt[row * NG + g];
            if (cmins[g] < gmin) gmin = cmins[g];
        }
        const float thr = gmin + MARGIN;

        float bestd = FLT_MAX;
        int bestj = NE;
        auto eval = [&](int j) {
            const float4* cr = (const float4*)(cb + (size_t)j * KDIM) + lid;
            const float4 c0 = cr[0], c1 = cr[32], c2 = cr[64], c3 = cr[96];
            float t = 0.f;
            t = fmaf(z0.x, c0.x, t); t = fmaf(z0.y, c0.y, t); t = fmaf(z0.z, c0.z, t); t = fmaf(z0.w, c0.w, t);
            t = fmaf(z1.x, c1.x, t); t = fmaf(z1.y, c1.y, t); t = fmaf(z1.z, c1.z, t); t = fmaf(z1.w, c1.w, t);
            t = fmaf(z2.x, c2.x, t); t = fmaf(z2.y, c2.y, t); t = fmaf(z2.z, c2.z, t); t = fmaf(z2.w, c2.w, t);
            t = fmaf(z3.x, c3.x, t); t = fmaf(z3.y, c3.y, t); t = fmaf(z3.z, c3.z, t); t = fmaf(z3.w, c3.w, t);
#pragma unroll
            for (int o = 16; o; o >>= 1) t += __shfl_xor_sync(0xffffffffu, t, o);
            // d = fl(fl(a + b) - 2c), exactly mirroring the reference
            float d = __fadd_rn(__fadd_rn(anorm, g_bnorm[j]), -2.0f * t);
            if (d < bestd || (d == bestd && j < bestj)) { bestd = d; bestj = j; }
        };

        for (int g = 0; g < NG; ++g) {
            if (cmins[g] > thr) continue;
            if (cnts[g] <= SLOTS) {
                const size_t base = ((size_t)row * NG + g) * SLOTS;
                for (int sI = 0; sI < cnts[g]; ++sI)
                    if (g_cd[base + sI] <= thr) eval(g_cj[base + sI]);
            } else {
                for (int c = 0; c < 128; ++c) eval(g * 128 + c);   // rare overflow
            }
        }

        // output: z_q_st (scalar stores; out+1 is float4-misaligned), loss partial
        const float4* cr = (const float4*)(cb + (size_t)bestj * KDIM) + lid;
        const float4 c0 = cr[0], c1 = cr[32], c2 = cr[64], c3 = cr[96];
        float* dst = out + 1 + (size_t)row * KDIM;
        {
            float t0 = __fsub_rn(c0.x, z0.x), t1 = __fsub_rn(c0.y, z0.y);
            float t2 = __fsub_rn(c0.z, z0.z), t3 = __fsub_rn(c0.w, z0.w);
            dst[4*lid+0] = __fadd_rn(z0.x, t0); dst[4*lid+1] = __fadd_rn(z0.y, t1);
            dst[4*lid+2] = __fadd_rn(z0.z, t2); dst[4*lid+3] = __fadd_rn(z0.w, t3);
            lsum += t0*t0 + t1*t1 + t2*t2 + t3*t3;
        }
        {
            float t0 = __fsub_rn(c1.x, z1.x), t1 = __fsub_rn(c1.y, z1.y);
            float t2 = __fsub_rn(c1.z, z1.z), t3 = __fsub_rn(c1.w, z1.w);
            dst[128+4*lid+0] = __fadd_rn(z1.x, t0); dst[128+4*lid+1] = __fadd_rn(z1.y, t1);
            dst[128+4*lid+2] = __fadd_rn(z1.z, t2); dst[128+4*lid+3] = __fadd_rn(z1.w, t3);
            lsum += t0*t0 + t1*t1 + t2*t2 + t3*t3;
        }
        {
            float t0 = __fsub_rn(c2.x, z2.x), t1 = __fsub_rn(c2.y, z2.y);
            float t2 = __fsub_rn(c2.z, z2.z), t3 = __fsub_rn(c2.w, z2.w);
            dst[256+4*lid+0] = __fadd_rn(z2.x, t0); dst[256+4*lid+1] = __fadd_rn(z2.y, t1);
            dst[256+4*lid+2] = __fadd_rn(z2.z, t2); dst[256+4*lid+3] = __fadd_rn(z2.w, t3);
            lsum += t0*t0 + t1*t1 + t2*t2 + t3*t3;
        }
        {
            float t0 = __fsub_rn(c3.x, z3.x), t1 = __fsub_rn(c3.y, z3.y);
            float t2 = __fsub_rn(c3.z, z3.z), t3 = __fsub_rn(c3.w, z3.w);
            dst[384+4*lid+0] = __fadd_rn(z3.x, t0); dst[384+4*lid+1] = __fadd_rn(z3.y, t1);
            dst[384+4*lid+2] = __fadd_rn(z3.z, t2); dst[384+4*lid+3] = __fadd_rn(z3.w, t3);
            lsum += t0*t0 + t1*t1 + t2*t2 + t3*t3;
        }

        if (lid == 0) {
            out[idx_base + row] = (float)bestj;
            atomicAdd(&g_counts[bestj], 1);
        }
    }

    // deterministic tile loss partial: lane-sum -> warp shfl -> fixed-order 8-warp sum
#pragma unroll
    for (int o = 16; o; o >>= 1) lsum += __shfl_xor_sync(0xffffffffu, lsum, o);
    __shared__ float red[8];
    if (lid == 0) red[wid] = lsum;
    __syncthreads();
    if (tid == 0) {
        float t = 0.f;
#pragma unroll
        for (int w = 0; w < 8; ++w) t += red[w];
        g_partials[tile] = t;
    }

    // ---- finalize (the CTA completing the last tile): loss + perplexity ----
    __threadfence();
    __syncthreads();
    __shared__ int s_fin;
    if (tid == 0) s_fin = (atomicAdd(&g_donecnt, 1) == TILES - 1);
    __syncthreads();
    if (!s_fin) return;
    __threadfence();

    __shared__ float red2[256];
    {
        float p = ((g_partials[tid] + g_partials[tid + 256])
                 + (g_partials[tid + 512] + g_partials[tid + 768]));
        red2[tid] = p;
        __syncthreads();
#pragma unroll
        for (int o = 128; o; o >>= 1) {
            if (tid < o) red2[tid] += red2[tid + o];
            __syncthreads();
        }
    }
    const float total = red2[0];
    __syncthreads();
    {
        float ent = 0.f;
#pragma unroll
        for (int q = 0; q < 4; ++q) {
            float e = (float)g_counts[tid + q * 256] * (1.0f / 65536.0f);
            ent += e * logf(e + 1e-10f);
        }
        red2[tid] = ent;
        __syncthreads();
#pragma unroll
        for (int o = 128; o; o >>= 1) {
            if (tid < o) red2[tid] += red2[tid + o];
            __syncthreads();
        }
    }
    if (tid == 0) {
        float m = total / 33554432.0f;
        out[0] = __fadd_rn(m, __fmul_rn(0.25f, m));
        out[out_size - 1] = expf(-red2[0]);
    }
}

// ---------------- launch ----------------
extern "C" void kernel_launch(void* const* d_in, const int* in_sizes, int n_in,
                              void* d_out, int out_size) {
    const float* z  = (const float*)d_in[0];
    const float* cb = (const float*)d_in[1];
    float* out = (float*)d_out;
    const int idx_base = out_size - 1 - N_ROWS;

    cudaFuncSetAttribute(gemm_kernel, cudaFuncAttributeMaxDynamicSharedMemorySize, GEMM_SMEM);

    prep_kernel<<<8704, 256>>>(z, cb);                                       // 0
    gemm_kernel<<<8192, 256, GEMM_SMEM>>>(z, cb, out, idx_base, out_size);   // 1
}